// round 14
// baseline (speedup 1.0000x reference)
#include <cuda_runtime.h>
#include <cuda_fp16.h>
#include <math.h>
#include <float.h>

#define T_    4
#define C_    64
#define WW    96
#define HW    9216
#define CI    16
#define PS    7
#define WS    21
#define NQX   24
#define NQ    576
#define NC    441
#define KSEL  100
#define SCALE 10.0f
#define RGN   27
#define RGN2  729
#define NT    256
#define B1P   56
#define QST   (RGN*WS)      // 567

// smem layout (float offsets)
#define SM_B1   0            // 896
#define SM_RG   896          // 11664 (b3 planar fp32; later aliased by fp16 b2)
#define SM_Q    12560        // 3970  (sort buffer B alias + off table)
#define SM_SRT  16530        // u64[512] = 1024 floats (sort buffer A)
#define SM_W    17556        // 104
#define SM_CID  17660        // 100
#define SM_RO   17760        // 147
#define SM_CO   17907        // 147
#define SM_GOFF 18054        // 729
#define SM_TOT  18783        // 75132 bytes

typedef unsigned long long ull;

// scratch: pixel-major layouts. b1/b3: [t*HW][16] fp32 ; b2h: [t*HW][16] fp16
__device__ __align__(16) float    g_b1[(size_t)T_*HW*CI];
__device__ __align__(16) float    g_b3[(size_t)T_*HW*CI];
__device__ __align__(16) unsigned g_b2h[(size_t)T_*HW*8];
__device__ __align__(16) float    g_acc[T_*CI*HW];

__device__ __forceinline__ int clipi(int v){ return min(max(v,0),95); }
__device__ __forceinline__ unsigned ordf(float f){
    unsigned b = __float_as_uint(f);
    return (b & 0x80000000u) ? ~b : (b | 0x80000000u);
}
__device__ __forceinline__ float iordf(unsigned u){
    unsigned b = (u & 0x80000000u) ? (u & 0x7FFFFFFFu) : ~u;
    return __uint_as_float(b);
}
__device__ __forceinline__ ull pack2(float lo, float hi){
    ull r; asm("mov.b64 %0, {%1, %2};" : "=l"(r) : "f"(lo), "f"(hi)); return r;
}
__device__ __forceinline__ void fma2(ull &acc, ull a, ull b){
    asm("fma.rn.f32x2 %0, %1, %2, %0;" : "+l"(acc) : "l"(a), "l"(b));
}
__device__ __forceinline__ float sum2(ull v){
    return __uint_as_float((unsigned)v) + __uint_as_float((unsigned)(v>>32));
}
__device__ __forceinline__ ull cmpshfl(ull v, int p, int j, int k){
    ull o = __shfl_xor_sync(0xffffffffu, v, j);
    bool keepMax = (((p & j)==0) == ((p & k)==0));
    ull mx = v > o ? v : o, mn = v > o ? o : v;
    return keepMax ? mx : mn;
}
__device__ __forceinline__ unsigned h2u(__half2 h){
    return *reinterpret_cast<unsigned*>(&h);
}
__device__ __forceinline__ __half2 u2h(unsigned u){
    return *reinterpret_cast<__half2*>(&u);
}

// ---------------------------------------------------------------- fused 3x conv1x1, 1 pixel/thread, 8-way co split
// grid = 8*144 blocks, 256 threads; sub = blockIdx.x/144 -> output channels [2*sub, 2*sub+2)
__global__ void __launch_bounds__(NT) k_proj(const float* __restrict__ vid,
                       const float* __restrict__ gw, const float* __restrict__ gb,
                       const float* __restrict__ tw, const float* __restrict__ tb,
                       const float* __restrict__ pw, const float* __restrict__ pb){
    __shared__ __align__(16) float sw[3*CI*C_ + 3*CI];
    for (int i=threadIdx.x; i<CI*C_; i+=NT){
        sw[i]          = gw[i];
        sw[CI*C_+i]    = tw[i];
        sw[2*CI*C_+i]  = pw[i];
    }
    if (threadIdx.x < CI){
        sw[3*CI*C_         + threadIdx.x] = gb[threadIdx.x];
        sw[3*CI*C_ +   CI  + threadIdx.x] = tb[threadIdx.x];
        sw[3*CI*C_ + 2*CI  + threadIdx.x] = pb[threadIdx.x];
    }

    int gid = blockIdx.x*NT + threadIdx.x;      // [0, 1152*256=294912)
    // zero g_acc: 294912 float2 = 589824 floats
    ((float2*)g_acc)[gid] = make_float2(0.f,0.f);
    __syncthreads();

    int sub  = blockIdx.x / 144;                // 0..7 -> output channels [2*sub, 2*sub+2)
    int base = (blockIdx.x % 144)*NT + threadIdx.x;   // pixel id in [0, T*HW)
    int t = base / HW, pix = base % HW;
    int o0 = sub*2;

    float a1[2], a2[2], a3[2];
    #pragma unroll
    for (int u=0;u<2;u++){
        a1[u] = sw[3*CI*C_ + o0+u];
        a2[u] = sw[3*CI*C_ + CI + o0+u];
        a3[u] = sw[3*CI*C_ + 2*CI + o0+u];
    }
    const float* vp = vid + (size_t)t*C_*HW + pix;
    #pragma unroll 4
    for (int c=0;c<C_;c+=4){
        float v0 = vp[c*HW], v1 = vp[(c+1)*HW], v2 = vp[(c+2)*HW], v3 = vp[(c+3)*HW];
        #pragma unroll
        for (int u=0;u<2;u++){
            int o = o0+u;
            float4 w1 = *(const float4*)(sw + o*C_ + c);
            float4 w2 = *(const float4*)(sw + CI*C_ + o*C_ + c);
            float4 w3 = *(const float4*)(sw + 2*CI*C_ + o*C_ + c);
            a1[u] += v0*w1.x + v1*w1.y + v2*w1.z + v3*w1.w;
            a2[u] += v0*w2.x + v1*w2.y + v2*w2.z + v3*w2.w;
            a3[u] += v0*w3.x + v1*w3.y + v2*w3.z + v3*w3.w;
        }
    }
    // pixel-major writes: float2 slots for b1/b3, single packed fp16 pair for b2
    ((float2*)g_b1)[(size_t)base*8 + sub] = make_float2(a1[0],a1[1]);
    ((float2*)g_b3)[(size_t)base*8 + sub] = make_float2(a3[0],a3[1]);
    g_b2h[(size_t)base*8 + sub] = h2u(__floats2half2_rn(a2[0], a2[1]));
}

// ---------------------------------------------------------------- main kernel (unchanged)
__global__ void __launch_bounds__(NT, 3) k_score(){
    extern __shared__ float sm[];
    float* s_b1 = sm + SM_B1;
    float* s_rg = sm + SM_RG;
    uint2* s_rgH = (uint2*)(sm + SM_RG);
    float* s_Q  = sm + SM_Q;
    ull*   s_srt = (ull*)(sm + SM_SRT);
    ull*   s_bufB = (ull*)(sm + SM_Q);
    float* s_w   = sm + SM_W;
    int*   s_cid = (int*)(sm + SM_CID);
    int*   s_ro  = (int*)(sm + SM_RO);
    int*   s_co  = (int*)(sm + SM_CO);
    int*   s_goff= (int*)(sm + SM_GOFF);
    int*   s_off = (int*)s_Q;

    int blk = blockIdx.x;
    int t = blk / NQ, q = blk % NQ;
    int qi = (q / NQX)*4, qj = (q % NQX)*4;
    int tid = threadIdx.x;

    int rmin = max(qi-10, 0), cmin = max(qj-10, 0);
    bool colAffine = (qj >= 12 && qj <= 76);

    // ---- tables
    if (tid < 147){
        int d_ = tid/7, e_ = tid%7;
        s_ro[tid] = min(clipi(qi + d_ - 10) + e_, 95) - rmin;
        s_co[tid] = min(clipi(qj + d_ - 10) + e_, 95) - cmin;
    }
    for (int i=tid; i<RGN2; i+=NT){
        int rr = i/RGN, cc = i - rr*RGN;
        s_goff[i] = min(rmin+rr,95)*WW + min(cmin+cc,95);
    }
    // b1 patch: 4 LDG.128 per patch pixel, scatter into pair layout
    if (tid < 49){
        int a = tid/7, b = tid - 7*a;
        int pp = min(qi+a,95)*WW + min(qj+b,95);
        const float4* b1p = (const float4*)g_b1 + ((size_t)t*HW + pp)*4;
        #pragma unroll
        for (int c=0;c<4;c++){
            float4 v = b1p[c];
            s_b1[(4*c+0)*B1P + a*8 + b] = v.x;
            s_b1[(4*c+1)*B1P + a*8 + b] = v.y;
            s_b1[(4*c+2)*B1P + a*8 + b] = v.z;
            s_b1[(4*c+3)*B1P + a*8 + b] = v.w;
        }
    }
    if (tid >= 64 && tid < 64+CI*7){
        int u = tid - 64, ci = u/7, a = u - 7*ci;
        s_b1[ci*B1P + a*8 + 7] = 0.f;
    }
    __syncthreads();

    // ---- load b3 region: 4 LDG.128 per pixel -> planar fp32 smem
    {
        const float4* b3p = (const float4*)g_b3 + (size_t)t*HW*4;
        for (int i=tid; i<RGN2; i+=NT){
            const float4* p = b3p + (size_t)s_goff[i]*4;
            float4 x0=p[0], x1=p[1], x2=p[2], x3=p[3];
            s_rg[ 0*RGN2+i]=x0.x; s_rg[ 1*RGN2+i]=x0.y; s_rg[ 2*RGN2+i]=x0.z; s_rg[ 3*RGN2+i]=x0.w;
            s_rg[ 4*RGN2+i]=x1.x; s_rg[ 5*RGN2+i]=x1.y; s_rg[ 6*RGN2+i]=x1.z; s_rg[ 7*RGN2+i]=x1.w;
            s_rg[ 8*RGN2+i]=x2.x; s_rg[ 9*RGN2+i]=x2.y; s_rg[10*RGN2+i]=x2.z; s_rg[11*RGN2+i]=x2.w;
            s_rg[12*RGN2+i]=x3.x; s_rg[13*RGN2+i]=x3.y; s_rg[14*RGN2+i]=x3.z; s_rg[15*RGN2+i]=x3.w;
        }
    }
    __syncthreads();

    // ---- stage 1: Q[a][r][dj] via f32x2, weights via LDS.128
    if (tid < 189){
        int r = tid/7, dj0 = (tid%7)*3;
        ull acc2[7][3];
        #pragma unroll
        for (int a=0;a<7;a++){ acc2[a][0]=0ull; acc2[a][1]=0ull; acc2[a][2]=0ull; }

        if (colAffine){
            for (int ci=0; ci<CI; ci++){
                const float* row = s_rg + ci*RGN2 + r*RGN + dj0;
                float win[9];
                #pragma unroll
                for (int j=0;j<9;j++) win[j] = row[j];
                ull wp[9];
                #pragma unroll
                for (int b=0;b<8;b++) wp[b] = pack2(win[b], win[b+1]);
                wp[8] = pack2(win[8], 0.f);
                const ulonglong2* wq2 = (const ulonglong2*)(s_b1 + ci*B1P);
                #pragma unroll
                for (int a=0;a<7;a++){
                    ulonglong2 wab = wq2[a*2], wcd = wq2[a*2+1];
                    #pragma unroll
                    for (int k=0;k<3;k++){
                        fma2(acc2[a][k], wab.x, wp[k]);
                        fma2(acc2[a][k], wab.y, wp[k+2]);
                        fma2(acc2[a][k], wcd.x, wp[k+4]);
                        fma2(acc2[a][k], wcd.y, wp[k+6]);
                    }
                }
            }
        } else {
            int clim = 95 - cmin;
            int cb[3];
            #pragma unroll
            for (int k=0;k<3;k++) cb[k] = s_co[(dj0+k)*7];
            for (int ci=0; ci<CI; ci++){
                const float* row = s_rg + ci*RGN2 + r*RGN;
                ull vp[3][4];
                #pragma unroll
                for (int k=0;k<3;k++){
                    float w0=row[min(cb[k]+0,clim)], w1=row[min(cb[k]+1,clim)];
                    float w2=row[min(cb[k]+2,clim)], w3=row[min(cb[k]+3,clim)];
                    float w4=row[min(cb[k]+4,clim)], w5=row[min(cb[k]+5,clim)];
                    float w6=row[min(cb[k]+6,clim)], w7=row[min(cb[k]+7,clim)];
                    vp[k][0]=pack2(w0,w1); vp[k][1]=pack2(w2,w3);
                    vp[k][2]=pack2(w4,w5); vp[k][3]=pack2(w6,w7);
                }
                const ulonglong2* wq2 = (const ulonglong2*)(s_b1 + ci*B1P);
                #pragma unroll
                for (int a=0;a<7;a++){
                    ulonglong2 wab = wq2[a*2], wcd = wq2[a*2+1];
                    #pragma unroll
                    for (int k=0;k<3;k++){
                        fma2(acc2[a][k], wab.x, vp[k][0]);
                        fma2(acc2[a][k], wab.y, vp[k][1]);
                        fma2(acc2[a][k], wcd.x, vp[k][2]);
                        fma2(acc2[a][k], wcd.y, vp[k][3]);
                    }
                }
            }
        }
        #pragma unroll
        for (int a=0;a<7;a++)
            #pragma unroll
            for (int k=0;k<3;k++)
                s_Q[a*QST + r*WS + dj0 + k] = sum2(acc2[a][k]);
    }
    __syncthreads();

    // ---- prefetch b2 (fp16-packed) chunks 0,1 into uint4 regs
    const uint4* b2p = (const uint4*)g_b2h + (size_t)t*HW*2;
    uint4 pa0, pa1, pb0, pb1;
    {
        size_t g0 = (size_t)s_goff[tid]*2;
        size_t g1 = (size_t)s_goff[tid+256]*2;
        pa0 = b2p[g0]; pa1 = b2p[g0+1];
        pb0 = b2p[g1]; pb1 = b2p[g1+1];
    }

    // ---- stage 2: keys straight into registers
    ull k0, k1;
    {
        int di = tid/WS, dj = tid - WS*di;
        float sc = 0.f;
        #pragma unroll
        for (int a=0;a<7;a++) sc += s_Q[a*QST + s_ro[di*7+a]*WS + dj];
        k0 = ((ull)ordf(sc) << 32) | (unsigned)tid;
        int c1 = tid + 256;
        k1 = 0ull;
        if (c1 < NC){
            int di1 = c1/WS, dj1 = c1 - WS*di1;
            float sc1 = 0.f;
            #pragma unroll
            for (int a=0;a<7;a++) sc1 += s_Q[a*QST + s_ro[di1*7+a]*WS + dj1];
            k1 = ((ull)ordf(sc1) << 32) | (unsigned)c1;
        }
    }
    __syncthreads();

    // ---- bitonic sort 512 descending: regs + shfl, 9 smem steps
    {
        int p1 = tid + 256;
        #pragma unroll
        for (int k=2; k<=32; k<<=1)
            #pragma unroll
            for (int j=k>>1; j; j>>=1){
                k0 = cmpshfl(k0, tid, j, k);
                k1 = cmpshfl(k1, p1,  j, k);
            }
        int tog = 0;
        #pragma unroll
        for (int k=64; k<=512; k<<=1){
            if (k == 512){ if (k0 < k1){ ull tt=k0; k0=k1; k1=tt; } }
            int jstart = (k>>1) > 128 ? 128 : (k>>1);
            for (int j=jstart; j>=32; j>>=1){
                ull* buf = tog ? s_bufB : s_srt;
                buf[tid] = k0; buf[p1] = k1;
                __syncthreads();
                int pt = tid ^ j;
                ull o0 = buf[pt], o1 = buf[pt+256];
                bool km0 = (((tid & j)==0) == (((tid) & k)==0));
                bool km1 = (((tid & j)==0) == (((p1 ) & k)==0));
                k0 = km0 ? (k0>o0?k0:o0) : (k0<o0?k0:o0);
                k1 = km1 ? (k1>o1?k1:o1) : (k1<o1?k1:o1);
                tog ^= 1;
            }
            #pragma unroll
            for (int j=16; j; j>>=1){
                k0 = cmpshfl(k0, tid, j, k);
                k1 = cmpshfl(k1, p1,  j, k);
            }
        }
    }
    if (tid < KSEL) s_srt[tid] = k0;
    __syncthreads();

    // ---- softmax over top-100
    {
        float maxs = iordf((unsigned)(s_srt[0] >> 32));
        if (tid < KSEL){
            ull key = s_srt[tid];
            float sc = iordf((unsigned)(key >> 32));
            s_w[tid]   = expf((sc - maxs)*SCALE);
            s_cid[tid] = (int)(key & 0x1FFu);
        }
        __syncthreads();
        if (tid < 32){
            float s = 0.f;
            for (int k=tid; k<KSEL; k+=32) s += s_w[k];
            #pragma unroll
            for (int o=16;o;o>>=1) s += __shfl_xor_sync(0xffffffffu, s, o);
            if (tid == 0) s_w[KSEL] = 1.f/s;
        }
        __syncthreads();
        if (tid < KSEL) s_w[tid] *= s_w[KSEL];
    }

    // ---- commit prefetched b2 (already fp16-packed) + third chunk + [k][49] offsets
    s_rgH[0*RGN2 + tid] = make_uint2(pa0.x, pa0.y);
    s_rgH[1*RGN2 + tid] = make_uint2(pa0.z, pa0.w);
    s_rgH[2*RGN2 + tid] = make_uint2(pa1.x, pa1.y);
    s_rgH[3*RGN2 + tid] = make_uint2(pa1.z, pa1.w);
    s_rgH[0*RGN2 + tid + 256] = make_uint2(pb0.x, pb0.y);
    s_rgH[1*RGN2 + tid + 256] = make_uint2(pb0.z, pb0.w);
    s_rgH[2*RGN2 + tid + 256] = make_uint2(pb1.x, pb1.y);
    s_rgH[3*RGN2 + tid + 256] = make_uint2(pb1.z, pb1.w);
    if (tid + 512 < RGN2){
        size_t g2 = (size_t)s_goff[tid+512]*2;
        uint4 c0 = b2p[g2], c1v = b2p[g2+1];
        s_rgH[0*RGN2 + tid + 512] = make_uint2(c0.x, c0.y);
        s_rgH[1*RGN2 + tid + 512] = make_uint2(c0.z, c0.w);
        s_rgH[2*RGN2 + tid + 512] = make_uint2(c1v.x, c1v.y);
        s_rgH[3*RGN2 + tid + 512] = make_uint2(c1v.z, c1v.w);
    }
    for (int i=tid; i<KSEL*49; i+=NT){
        int k = i/49, p = i - 49*k;
        int c = s_cid[k];
        int pa = p/7, pb = p - 7*pa;
        s_off[k*49 + p] = s_ro[(c/WS)*7 + pa]*RGN + s_co[(c%WS)*7 + pb];
    }
    __syncthreads();

    // ---- aggregation: 196 threads, per-k: LDS.32 off + LDS.64 fp16 gather
    if (tid < 196){
        int p   = tid % 49;
        int cig = tid / 49;
        const uint2* rg = s_rgH + cig*RGN2;
        float a0=0.f, a1=0.f, a2=0.f, a3=0.f;
        #pragma unroll 2
        for (int k=0; k<KSEL; k+=4){
            float4 w4 = *(const float4*)(s_w + k);
            #pragma unroll
            for (int u=0; u<4; u++){
                float w = (u==0)?w4.x:(u==1)?w4.y:(u==2)?w4.z:w4.w;
                int off = s_off[(k+u)*49 + p];
                uint2 v = rg[off];
                float2 f0 = __half22float2(u2h(v.x));
                float2 f1 = __half22float2(u2h(v.y));
                a0 += w*f0.x; a1 += w*f0.y; a2 += w*f1.x; a3 += w*f1.y;
            }
        }
        int pa = p/7, pb = p - 7*pa;
        int pix = min(qi+pa,95)*WW + min(qj+pb,95);
        float* accb = g_acc + (size_t)(t*CI + cig*4)*HW + pix;
        atomicAdd(accb,        a0);
        atomicAdd(accb +   HW, a1);
        atomicAdd(accb + 2*HW, a2);
        atomicAdd(accb + 3*HW, a3);
    }
}

// ---------------------------------------------------------------- final: 1 pixel/thread, 4-way co split
// grid = 4*144 blocks, 256 threads; sub -> co range [16*sub, 16*sub+16)
__global__ void __launch_bounds__(NT) k_final(const float* __restrict__ vid, const float* __restrict__ Ww,
                        const float* __restrict__ Wb, float* __restrict__ out){
    __shared__ __align__(16) float sw[C_*CI + C_];
    for (int i=threadIdx.x; i<C_*CI; i+=NT) sw[i] = Ww[i];
    if (threadIdx.x < C_) sw[C_*CI+threadIdx.x] = Wb[threadIdx.x];
    __syncthreads();

    int sub  = blockIdx.x / 144;
    int base = (blockIdx.x % 144)*NT + threadIdx.x;
    int t = base / HW, pix = base % HW;
    int row = pix / WW, col = pix - row*WW;

    int cr = 0, cc = 0;
    #pragma unroll
    for (int a=0;a<7;a++){
        int v = row - a; cr += (v >= 0 && v <= 92 && (v & 3) == 0);
        int u = col - a; cc += (u >= 0 && u <= 92 && (u & 3) == 0);
    }
    if (row == 95) cr += 3;
    if (col == 95) cc += 3;
    float inv = 1.f / (float)(cr*cc);

    float y[CI];
    #pragma unroll
    for (int ci=0;ci<CI;ci++) y[ci] = g_acc[(t*CI+ci)*HW + pix]*inv;

    const float* vp = vid + (size_t)t*C_*HW + pix;
    float*       op = out + (size_t)t*C_*HW + pix;
    int co0 = sub*16;
    #pragma unroll 4
    for (int u=0; u<16; u++){
        int co = co0 + u;
        float s = sw[C_*CI+co];
        #pragma unroll
        for (int g=0; g<4; g++){
            float4 w4 = *(const float4*)(sw + co*CI + 4*g);
            s += w4.x*y[4*g] + w4.y*y[4*g+1] + w4.z*y[4*g+2] + w4.w*y[4*g+3];
        }
        op[co*HW] = vp[co*HW] + s;
    }
}

// ---------------------------------------------------------------- launch
extern "C" void kernel_launch(void* const* d_in, const int* in_sizes, int n_in,
                              void* d_out, int out_size){
    const float* vid  = (const float*)d_in[0];
    const float* g_w  = (const float*)d_in[1];
    const float* g_b  = (const float*)d_in[2];
    const float* th_w = (const float*)d_in[3];
    const float* th_b = (const float*)d_in[4];
    const float* ph_w = (const float*)d_in[5];
    const float* ph_b = (const float*)d_in[6];
    const float* W_w  = (const float*)d_in[7];
    const float* W_b  = (const float*)d_in[8];
    float* out = (float*)d_out;

    const int SMEM = SM_TOT * 4;   // 75132 B
    cudaFuncSetAttribute(k_score, cudaFuncAttributeMaxDynamicSharedMemorySize, SMEM);

    k_proj  <<<8*144, NT>>>(vid, g_w, g_b, th_w, th_b, ph_w, ph_b);
    k_score <<<T_*NQ, NT, SMEM>>>();
    k_final <<<4*144, NT>>>(vid, W_w, W_b, out);
}

// round 15
// speedup vs baseline: 1.0054x; 1.0054x over previous
#include <cuda_runtime.h>
#include <cuda_fp16.h>
#include <math.h>
#include <float.h>

#define T_    4
#define C_    64
#define WW    96
#define HW    9216
#define CI    16
#define PS    7
#define WS    21
#define NQX   24
#define NQ    576
#define NC    441
#define KSEL  100
#define SCALE 10.0f
#define RGN   27
#define RGN2  729
#define NT    256
#define NTC   128
#define B1P   56
#define QST   (RGN*WS)      // 567

// smem layout (float offsets)
#define SM_B1   0            // 896
#define SM_RG   896          // 11664 (b3 planar fp32; later aliased by fp16 b2)
#define SM_Q    12560        // 3970  (sort buffer B alias + off table)
#define SM_SRT  16530        // u64[512] = 1024 floats (sort buffer A)
#define SM_W    17556        // 104
#define SM_CID  17660        // 100
#define SM_RO   17760        // 147
#define SM_CO   17907        // 147
#define SM_GOFF 18054        // 729
#define SM_TOT  18783        // 75132 bytes

typedef unsigned long long ull;

// scratch: pixel-major layouts. b1/b3: [t*HW][16] fp32 ; b2h: [t*HW][16] fp16
__device__ __align__(16) float    g_b1[(size_t)T_*HW*CI];
__device__ __align__(16) float    g_b3[(size_t)T_*HW*CI];
__device__ __align__(16) unsigned g_b2h[(size_t)T_*HW*8];
__device__ __align__(16) float    g_acc[T_*CI*HW];

__device__ __forceinline__ int clipi(int v){ return min(max(v,0),95); }
__device__ __forceinline__ unsigned ordf(float f){
    unsigned b = __float_as_uint(f);
    return (b & 0x80000000u) ? ~b : (b | 0x80000000u);
}
__device__ __forceinline__ float iordf(unsigned u){
    unsigned b = (u & 0x80000000u) ? (u & 0x7FFFFFFFu) : ~u;
    return __uint_as_float(b);
}
__device__ __forceinline__ ull pack2(float lo, float hi){
    ull r; asm("mov.b64 %0, {%1, %2};" : "=l"(r) : "f"(lo), "f"(hi)); return r;
}
__device__ __forceinline__ void fma2(ull &acc, ull a, ull b){
    asm("fma.rn.f32x2 %0, %1, %2, %0;" : "+l"(acc) : "l"(a), "l"(b));
}
__device__ __forceinline__ float sum2(ull v){
    return __uint_as_float((unsigned)v) + __uint_as_float((unsigned)(v>>32));
}
__device__ __forceinline__ ull cmpshfl(ull v, int p, int j, int k){
    ull o = __shfl_xor_sync(0xffffffffu, v, j);
    bool keepMax = (((p & j)==0) == ((p & k)==0));
    ull mx = v > o ? v : o, mn = v > o ? o : v;
    return keepMax ? mx : mn;
}
__device__ __forceinline__ unsigned h2u(__half2 h){
    return *reinterpret_cast<unsigned*>(&h);
}
__device__ __forceinline__ __half2 u2h(unsigned u){
    return *reinterpret_cast<__half2*>(&u);
}

// ---------------------------------------------------------------- fused 3x conv1x1 (R11 config: 4-way split, 1 px/thread)
__global__ void __launch_bounds__(NT) k_proj(const float* __restrict__ vid,
                       const float* __restrict__ gw, const float* __restrict__ gb,
                       const float* __restrict__ tw, const float* __restrict__ tb,
                       const float* __restrict__ pw, const float* __restrict__ pb){
    __shared__ __align__(16) float sw[3*CI*C_ + 3*CI];
    for (int i=threadIdx.x; i<CI*C_; i+=NT){
        sw[i]          = gw[i];
        sw[CI*C_+i]    = tw[i];
        sw[2*CI*C_+i]  = pw[i];
    }
    if (threadIdx.x < CI){
        sw[3*CI*C_         + threadIdx.x] = gb[threadIdx.x];
        sw[3*CI*C_ +   CI  + threadIdx.x] = tb[threadIdx.x];
        sw[3*CI*C_ + 2*CI  + threadIdx.x] = pb[threadIdx.x];
    }

    int gid = blockIdx.x*NT + threadIdx.x;      // [0, 576*256=147456)
    ((float4*)g_acc)[gid] = make_float4(0.f,0.f,0.f,0.f);
    __syncthreads();

    int sub = blockIdx.x / 144;                 // output channels [4*sub, 4*sub+4)
    int pid = (blockIdx.x % 144)*NT + threadIdx.x;   // [0, T*HW)
    int t = pid / HW, pix = pid % HW;
    int o0 = sub*4;

    float a1[4], a2[4], a3[4];
    #pragma unroll
    for (int u=0;u<4;u++){
        a1[u] = sw[3*CI*C_ + o0+u];
        a2[u] = sw[3*CI*C_ + CI + o0+u];
        a3[u] = sw[3*CI*C_ + 2*CI + o0+u];
    }
    const float* vp = vid + (size_t)t*C_*HW + pix;
    #pragma unroll 4
    for (int c=0;c<C_;c+=4){
        float v0 = vp[c*HW], v1 = vp[(c+1)*HW], v2 = vp[(c+2)*HW], v3 = vp[(c+3)*HW];
        #pragma unroll
        for (int u=0;u<4;u++){
            int o = o0+u;
            float4 w1 = *(const float4*)(sw + o*C_ + c);
            float4 w2 = *(const float4*)(sw + CI*C_ + o*C_ + c);
            float4 w3 = *(const float4*)(sw + 2*CI*C_ + o*C_ + c);
            a1[u] += v0*w1.x + v1*w1.y + v2*w1.z + v3*w1.w;
            a2[u] += v0*w2.x + v1*w2.y + v2*w2.z + v3*w2.w;
            a3[u] += v0*w3.x + v1*w3.y + v2*w3.z + v3*w3.w;
        }
    }
    ((float4*)g_b1)[(size_t)pid*4 + sub] = make_float4(a1[0],a1[1],a1[2],a1[3]);
    ((float4*)g_b3)[(size_t)pid*4 + sub] = make_float4(a3[0],a3[1],a3[2],a3[3]);
    uint2 u2v;
    u2v.x = h2u(__floats2half2_rn(a2[0], a2[1]));
    u2v.y = h2u(__floats2half2_rn(a2[2], a2[3]));
    ((uint2*)g_b2h)[(size_t)pid*4 + sub] = u2v;
}

// ---------------------------------------------------------------- main kernel (unchanged verified core)
__global__ void __launch_bounds__(NT, 3) k_score(){
    extern __shared__ float sm[];
    float* s_b1 = sm + SM_B1;
    float* s_rg = sm + SM_RG;
    uint2* s_rgH = (uint2*)(sm + SM_RG);
    float* s_Q  = sm + SM_Q;
    ull*   s_srt = (ull*)(sm + SM_SRT);
    ull*   s_bufB = (ull*)(sm + SM_Q);
    float* s_w   = sm + SM_W;
    int*   s_cid = (int*)(sm + SM_CID);
    int*   s_ro  = (int*)(sm + SM_RO);
    int*   s_co  = (int*)(sm + SM_CO);
    int*   s_goff= (int*)(sm + SM_GOFF);
    int*   s_off = (int*)s_Q;

    int blk = blockIdx.x;
    int t = blk / NQ, q = blk % NQ;
    int qi = (q / NQX)*4, qj = (q % NQX)*4;
    int tid = threadIdx.x;

    int rmin = max(qi-10, 0), cmin = max(qj-10, 0);
    bool colAffine = (qj >= 12 && qj <= 76);

    // ---- tables
    if (tid < 147){
        int d_ = tid/7, e_ = tid%7;
        s_ro[tid] = min(clipi(qi + d_ - 10) + e_, 95) - rmin;
        s_co[tid] = min(clipi(qj + d_ - 10) + e_, 95) - cmin;
    }
    for (int i=tid; i<RGN2; i+=NT){
        int rr = i/RGN, cc = i - rr*RGN;
        s_goff[i] = min(rmin+rr,95)*WW + min(cmin+cc,95);
    }
    // b1 patch: 4 LDG.128 per patch pixel, scatter into pair layout
    if (tid < 49){
        int a = tid/7, b = tid - 7*a;
        int pp = min(qi+a,95)*WW + min(qj+b,95);
        const float4* b1p = (const float4*)g_b1 + ((size_t)t*HW + pp)*4;
        #pragma unroll
        for (int c=0;c<4;c++){
            float4 v = b1p[c];
            s_b1[(4*c+0)*B1P + a*8 + b] = v.x;
            s_b1[(4*c+1)*B1P + a*8 + b] = v.y;
            s_b1[(4*c+2)*B1P + a*8 + b] = v.z;
            s_b1[(4*c+3)*B1P + a*8 + b] = v.w;
        }
    }
    if (tid >= 64 && tid < 64+CI*7){
        int u = tid - 64, ci = u/7, a = u - 7*ci;
        s_b1[ci*B1P + a*8 + 7] = 0.f;
    }
    __syncthreads();

    // ---- load b3 region: 4 LDG.128 per pixel -> planar fp32 smem
    {
        const float4* b3p = (const float4*)g_b3 + (size_t)t*HW*4;
        for (int i=tid; i<RGN2; i+=NT){
            const float4* p = b3p + (size_t)s_goff[i]*4;
            float4 x0=p[0], x1=p[1], x2=p[2], x3=p[3];
            s_rg[ 0*RGN2+i]=x0.x; s_rg[ 1*RGN2+i]=x0.y; s_rg[ 2*RGN2+i]=x0.z; s_rg[ 3*RGN2+i]=x0.w;
            s_rg[ 4*RGN2+i]=x1.x; s_rg[ 5*RGN2+i]=x1.y; s_rg[ 6*RGN2+i]=x1.z; s_rg[ 7*RGN2+i]=x1.w;
            s_rg[ 8*RGN2+i]=x2.x; s_rg[ 9*RGN2+i]=x2.y; s_rg[10*RGN2+i]=x2.z; s_rg[11*RGN2+i]=x2.w;
            s_rg[12*RGN2+i]=x3.x; s_rg[13*RGN2+i]=x3.y; s_rg[14*RGN2+i]=x3.z; s_rg[15*RGN2+i]=x3.w;
        }
    }
    __syncthreads();

    // ---- stage 1: Q[a][r][dj] via f32x2, weights via LDS.128
    if (tid < 189){
        int r = tid/7, dj0 = (tid%7)*3;
        ull acc2[7][3];
        #pragma unroll
        for (int a=0;a<7;a++){ acc2[a][0]=0ull; acc2[a][1]=0ull; acc2[a][2]=0ull; }

        if (colAffine){
            for (int ci=0; ci<CI; ci++){
                const float* row = s_rg + ci*RGN2 + r*RGN + dj0;
                float win[9];
                #pragma unroll
                for (int j=0;j<9;j++) win[j] = row[j];
                ull wp[9];
                #pragma unroll
                for (int b=0;b<8;b++) wp[b] = pack2(win[b], win[b+1]);
                wp[8] = pack2(win[8], 0.f);
                const ulonglong2* wq2 = (const ulonglong2*)(s_b1 + ci*B1P);
                #pragma unroll
                for (int a=0;a<7;a++){
                    ulonglong2 wab = wq2[a*2], wcd = wq2[a*2+1];
                    #pragma unroll
                    for (int k=0;k<3;k++){
                        fma2(acc2[a][k], wab.x, wp[k]);
                        fma2(acc2[a][k], wab.y, wp[k+2]);
                        fma2(acc2[a][k], wcd.x, wp[k+4]);
                        fma2(acc2[a][k], wcd.y, wp[k+6]);
                    }
                }
            }
        } else {
            int clim = 95 - cmin;
            int cb[3];
            #pragma unroll
            for (int k=0;k<3;k++) cb[k] = s_co[(dj0+k)*7];
            for (int ci=0; ci<CI; ci++){
                const float* row = s_rg + ci*RGN2 + r*RGN;
                ull vp[3][4];
                #pragma unroll
                for (int k=0;k<3;k++){
                    float w0=row[min(cb[k]+0,clim)], w1=row[min(cb[k]+1,clim)];
                    float w2=row[min(cb[k]+2,clim)], w3=row[min(cb[k]+3,clim)];
                    float w4=row[min(cb[k]+4,clim)], w5=row[min(cb[k]+5,clim)];
                    float w6=row[min(cb[k]+6,clim)], w7=row[min(cb[k]+7,clim)];
                    vp[k][0]=pack2(w0,w1); vp[k][1]=pack2(w2,w3);
                    vp[k][2]=pack2(w4,w5); vp[k][3]=pack2(w6,w7);
                }
                const ulonglong2* wq2 = (const ulonglong2*)(s_b1 + ci*B1P);
                #pragma unroll
                for (int a=0;a<7;a++){
                    ulonglong2 wab = wq2[a*2], wcd = wq2[a*2+1];
                    #pragma unroll
                    for (int k=0;k<3;k++){
                        fma2(acc2[a][k], wab.x, vp[k][0]);
                        fma2(acc2[a][k], wab.y, vp[k][1]);
                        fma2(acc2[a][k], wcd.x, vp[k][2]);
                        fma2(acc2[a][k], wcd.y, vp[k][3]);
                    }
                }
            }
        }
        #pragma unroll
        for (int a=0;a<7;a++)
            #pragma unroll
            for (int k=0;k<3;k++)
                s_Q[a*QST + r*WS + dj0 + k] = sum2(acc2[a][k]);
    }
    __syncthreads();

    // ---- prefetch b2 (fp16-packed) chunks 0,1 into uint4 regs
    const uint4* b2p = (const uint4*)g_b2h + (size_t)t*HW*2;
    uint4 pa0, pa1, pb0, pb1;
    {
        size_t g0 = (size_t)s_goff[tid]*2;
        size_t g1 = (size_t)s_goff[tid+256]*2;
        pa0 = b2p[g0]; pa1 = b2p[g0+1];
        pb0 = b2p[g1]; pb1 = b2p[g1+1];
    }

    // ---- stage 2: keys straight into registers
    ull k0, k1;
    {
        int di = tid/WS, dj = tid - WS*di;
        float sc = 0.f;
        #pragma unroll
        for (int a=0;a<7;a++) sc += s_Q[a*QST + s_ro[di*7+a]*WS + dj];
        k0 = ((ull)ordf(sc) << 32) | (unsigned)tid;
        int c1 = tid + 256;
        k1 = 0ull;
        if (c1 < NC){
            int di1 = c1/WS, dj1 = c1 - WS*di1;
            float sc1 = 0.f;
            #pragma unroll
            for (int a=0;a<7;a++) sc1 += s_Q[a*QST + s_ro[di1*7+a]*WS + dj1];
            k1 = ((ull)ordf(sc1) << 32) | (unsigned)c1;
        }
    }
    __syncthreads();

    // ---- bitonic sort 512 descending: regs + shfl, 9 smem steps
    {
        int p1 = tid + 256;
        #pragma unroll
        for (int k=2; k<=32; k<<=1)
            #pragma unroll
            for (int j=k>>1; j; j>>=1){
                k0 = cmpshfl(k0, tid, j, k);
                k1 = cmpshfl(k1, p1,  j, k);
            }
        int tog = 0;
        #pragma unroll
        for (int k=64; k<=512; k<<=1){
            if (k == 512){ if (k0 < k1){ ull tt=k0; k0=k1; k1=tt; } }
            int jstart = (k>>1) > 128 ? 128 : (k>>1);
            for (int j=jstart; j>=32; j>>=1){
                ull* buf = tog ? s_bufB : s_srt;
                buf[tid] = k0; buf[p1] = k1;
                __syncthreads();
                int pt = tid ^ j;
                ull o0 = buf[pt], o1 = buf[pt+256];
                bool km0 = (((tid & j)==0) == (((tid) & k)==0));
                bool km1 = (((tid & j)==0) == (((p1 ) & k)==0));
                k0 = km0 ? (k0>o0?k0:o0) : (k0<o0?k0:o0);
                k1 = km1 ? (k1>o1?k1:o1) : (k1<o1?k1:o1);
                tog ^= 1;
            }
            #pragma unroll
            for (int j=16; j; j>>=1){
                k0 = cmpshfl(k0, tid, j, k);
                k1 = cmpshfl(k1, p1,  j, k);
            }
        }
    }
    if (tid < KSEL) s_srt[tid] = k0;
    __syncthreads();

    // ---- softmax over top-100
    {
        float maxs = iordf((unsigned)(s_srt[0] >> 32));
        if (tid < KSEL){
            ull key = s_srt[tid];
            float sc = iordf((unsigned)(key >> 32));
            s_w[tid]   = expf((sc - maxs)*SCALE);
            s_cid[tid] = (int)(key & 0x1FFu);
        }
        __syncthreads();
        if (tid < 32){
            float s = 0.f;
            for (int k=tid; k<KSEL; k+=32) s += s_w[k];
            #pragma unroll
            for (int o=16;o;o>>=1) s += __shfl_xor_sync(0xffffffffu, s, o);
            if (tid == 0) s_w[KSEL] = 1.f/s;
        }
        __syncthreads();
        if (tid < KSEL) s_w[tid] *= s_w[KSEL];
    }

    // ---- commit prefetched b2 (already fp16-packed) + third chunk + [k][49] offsets
    s_rgH[0*RGN2 + tid] = make_uint2(pa0.x, pa0.y);
    s_rgH[1*RGN2 + tid] = make_uint2(pa0.z, pa0.w);
    s_rgH[2*RGN2 + tid] = make_uint2(pa1.x, pa1.y);
    s_rgH[3*RGN2 + tid] = make_uint2(pa1.z, pa1.w);
    s_rgH[0*RGN2 + tid + 256] = make_uint2(pb0.x, pb0.y);
    s_rgH[1*RGN2 + tid + 256] = make_uint2(pb0.z, pb0.w);
    s_rgH[2*RGN2 + tid + 256] = make_uint2(pb1.x, pb1.y);
    s_rgH[3*RGN2 + tid + 256] = make_uint2(pb1.z, pb1.w);
    if (tid + 512 < RGN2){
        size_t g2 = (size_t)s_goff[tid+512]*2;
        uint4 c0 = b2p[g2], c1v = b2p[g2+1];
        s_rgH[0*RGN2 + tid + 512] = make_uint2(c0.x, c0.y);
        s_rgH[1*RGN2 + tid + 512] = make_uint2(c0.z, c0.w);
        s_rgH[2*RGN2 + tid + 512] = make_uint2(c1v.x, c1v.y);
        s_rgH[3*RGN2 + tid + 512] = make_uint2(c1v.z, c1v.w);
    }
    for (int i=tid; i<KSEL*49; i+=NT){
        int k = i/49, p = i - 49*k;
        int c = s_cid[k];
        int pa = p/7, pb = p - 7*pa;
        s_off[k*49 + p] = s_ro[(c/WS)*7 + pa]*RGN + s_co[(c%WS)*7 + pb];
    }
    __syncthreads();

    // ---- aggregation: 196 threads, per-k: LDS.32 off + LDS.64 fp16 gather
    if (tid < 196){
        int p   = tid % 49;
        int cig = tid / 49;
        const uint2* rg = s_rgH + cig*RGN2;
        float a0=0.f, a1=0.f, a2=0.f, a3=0.f;
        #pragma unroll 2
        for (int k=0; k<KSEL; k+=4){
            float4 w4 = *(const float4*)(s_w + k);
            #pragma unroll
            for (int u=0; u<4; u++){
                float w = (u==0)?w4.x:(u==1)?w4.y:(u==2)?w4.z:w4.w;
                int off = s_off[(k+u)*49 + p];
                uint2 v = rg[off];
                float2 f0 = __half22float2(u2h(v.x));
                float2 f1 = __half22float2(u2h(v.y));
                a0 += w*f0.x; a1 += w*f0.y; a2 += w*f1.x; a3 += w*f1.y;
            }
        }
        int pa = p/7, pb = p - 7*pa;
        int pix = min(qi+pa,95)*WW + min(qj+pb,95);
        float* accb = g_acc + (size_t)(t*CI + cig*4)*HW + pix;
        atomicAdd(accb,        a0);
        atomicAdd(accb +   HW, a1);
        atomicAdd(accb + 2*HW, a2);
        atomicAdd(accb + 3*HW, a3);
    }
}

// ---------------------------------------------------------------- final (R13 config: 2 px/thread, 128-thr, 2-way co split)
__global__ void __launch_bounds__(NTC) k_final(const float* __restrict__ vid, const float* __restrict__ Ww,
                        const float* __restrict__ Wb, float* __restrict__ out){
    __shared__ __align__(16) float sw[C_*CI + C_];
    for (int i=threadIdx.x; i<C_*CI; i+=NTC) sw[i] = Ww[i];
    if (threadIdx.x < C_) sw[C_*CI+threadIdx.x] = Wb[threadIdx.x];
    __syncthreads();

    int sub  = blockIdx.x / 144;                // co range [32*sub, 32*sub+32)
    int base = (blockIdx.x % 144)*256 + threadIdx.x;
    int t = base / HW, pix = base % HW;

    float inv0, inv1;
    #pragma unroll
    for (int pp=0; pp<2; pp++){
        int px = pix + pp*128;
        int row = px / WW, col = px - row*WW;
        int cr = 0, cc = 0;
        #pragma unroll
        for (int a=0;a<7;a++){
            int v = row - a; cr += (v >= 0 && v <= 92 && (v & 3) == 0);
            int u = col - a; cc += (u >= 0 && u <= 92 && (u & 3) == 0);
        }
        if (row == 95) cr += 3;
        if (col == 95) cc += 3;
        float inv = 1.f / (float)(cr*cc);
        if (pp == 0) inv0 = inv; else inv1 = inv;
    }

    float y0[CI], y1[CI];
    #pragma unroll
    for (int ci=0;ci<CI;ci++){
        y0[ci] = g_acc[(t*CI+ci)*HW + pix]       * inv0;
        y1[ci] = g_acc[(t*CI+ci)*HW + pix + 128] * inv1;
    }

    const float* vp = vid + (size_t)t*C_*HW + pix;
    float*       op = out + (size_t)t*C_*HW + pix;
    int co0 = sub*32;
    #pragma unroll 4
    for (int u=0; u<32; u++){
        int co = co0 + u;
        float bias = sw[C_*CI+co];
        float s0 = bias, s1 = bias;
        #pragma unroll
        for (int g=0; g<4; g++){
            float4 w4 = *(const float4*)(sw + co*CI + 4*g);
            s0 += w4.x*y0[4*g] + w4.y*y0[4*g+1] + w4.z*y0[4*g+2] + w4.w*y0[4*g+3];
            s1 += w4.x*y1[4*g] + w4.y*y1[4*g+1] + w4.z*y1[4*g+2] + w4.w*y1[4*g+3];
        }
        op[co*HW]       = vp[co*HW]       + s0;
        op[co*HW + 128] = vp[co*HW + 128] + s1;
    }
}

// ---------------------------------------------------------------- launch
extern "C" void kernel_launch(void* const* d_in, const int* in_sizes, int n_in,
                              void* d_out, int out_size){
    const float* vid  = (const float*)d_in[0];
    const float* g_w  = (const float*)d_in[1];
    const float* g_b  = (const float*)d_in[2];
    const float* th_w = (const float*)d_in[3];
    const float* th_b = (const float*)d_in[4];
    const float* ph_w = (const float*)d_in[5];
    const float* ph_b = (const float*)d_in[6];
    const float* W_w  = (const float*)d_in[7];
    const float* W_b  = (const float*)d_in[8];
    float* out = (float*)d_out;

    const int SMEM = SM_TOT * 4;   // 75132 B
    cudaFuncSetAttribute(k_score, cudaFuncAttributeMaxDynamicSharedMemorySize, SMEM);

    k_proj  <<<4*144, NT>>>(vid, g_w, g_b, th_w, th_b, ph_w, ph_b);
    k_score <<<T_*NQ, NT, SMEM>>>();
    k_final <<<2*144, NTC>>>(vid, W_w, W_b, out);
}